// round 16
// baseline (speedup 1.0000x reference)
#include <cuda_runtime.h>
#include <cuda_bf16.h>
#include <math.h>
#include <stdint.h>

// ---------------------------------------------------------------------------
// Attention_51977694216863 (B=4, S=2048, D=2048, fp32).
// mma.sync bf16x3 pipeline. CTA tile 128x256, warp tile 64x64.
// Round-14 fix: STAGES=4 (round-13 used 3 stages with prefetch distance 3 ->
// (it+3)%3 == it%3, i.e. cp.async overwrote the stage being read: data race).
// C = scale*(A @ B^T)[+bias][causal|K-limit]; D += Alo*Bhi + Ahi*Blo + Ahi*Bhi
// ---------------------------------------------------------------------------

#define BM 128
#define BN 256
#define BK 32
#define NT 256
#define STAGES 4
#define A_BYTES 8192                        // 128 rows x 32 bf16 x 2B
#define B_BYTES 16384                       // 256 rows x 32 bf16 x 2B
#define STAGE_BYTES (2 * A_BYTES + 2 * B_BYTES)   // Ah, Al, Bh, Bl = 49152
#define OFF_AL (A_BYTES)
#define OFF_BH (2 * A_BYTES)
#define OFF_BL (2 * A_BYTES + B_BYTES)
#define SMEM_TOTAL (STAGES * STAGE_BYTES)   // 196608 B (< 227KB cap)

// ---------------------------------------------------------------------------
// Pooled scratch (allocation-free rule: one __device__ global), 285MB peak.
//   [0,2U): xh,xl -> later fp32 scores s   [2U,4U): qh,ql -> attn hi/lo
//   [4U,6U): kh,kl -> ctx hi/lo            [6U,8U): vth,vtl
//   [8U,+2W): wh,wl (re-split per projection)
// ---------------------------------------------------------------------------
#define UNIT (8192L * 2048 * 2)
#define WUNIT (2048L * 2048 * 2)
__device__ __align__(256) uint8_t g_pool[8 * UNIT + 2 * WUNIT];

// ---------------------------------------------------------------------------
// helpers
// ---------------------------------------------------------------------------
__device__ __forceinline__ uint32_t smem_u32(const void* p) {
    uint32_t a;
    asm("{ .reg .u64 t; cvta.to.shared.u64 t, %1; cvt.u32.u64 %0, t; }"
        : "=r"(a) : "l"(p));
    return a;
}

__device__ __forceinline__ uint32_t cvt_bf16x2(float lo_e, float hi_e) {
    uint32_t r;
    asm("cvt.rn.bf16x2.f32 %0, %1, %2;" : "=r"(r) : "f"(hi_e), "f"(lo_e));
    return r;  // low half = lo_e, high half = hi_e
}
__device__ __forceinline__ void split2(float e0, float e1, uint32_t& hi, uint32_t& lo) {
    uint32_t h = cvt_bf16x2(e0, e1);
    float f0 = __uint_as_float(h << 16);
    float f1 = __uint_as_float(h & 0xffff0000u);
    lo = cvt_bf16x2(e0 - f0, e1 - f1);
    hi = h;
}

__device__ __forceinline__ void mma_bf16(float* c, const uint32_t* a,
                                         uint32_t b0, uint32_t b1) {
    asm volatile(
        "mma.sync.aligned.m16n8k16.row.col.f32.bf16.bf16.f32 "
        "{%0,%1,%2,%3}, {%4,%5,%6,%7}, {%8,%9}, {%0,%1,%2,%3};"
        : "+f"(c[0]), "+f"(c[1]), "+f"(c[2]), "+f"(c[3])
        : "r"(a[0]), "r"(a[1]), "r"(a[2]), "r"(a[3]), "r"(b0), "r"(b1));
}

__device__ __forceinline__ void ldsm4(uint32_t* r, uint32_t addr) {
    asm volatile("ldmatrix.sync.aligned.m8n8.x4.shared.b16 {%0,%1,%2,%3}, [%4];"
                 : "=r"(r[0]), "=r"(r[1]), "=r"(r[2]), "=r"(r[3]) : "r"(addr));
}

__device__ __forceinline__ void cp16(uint32_t dst, const void* src) {
    asm volatile("cp.async.cg.shared.global [%0], [%1], 16;"
                 :: "r"(dst), "l"(src));
}
__device__ __forceinline__ void cp_commit() {
    asm volatile("cp.async.commit_group;" ::: "memory");
}
__device__ __forceinline__ void cp_wait2() {
    asm volatile("cp.async.wait_group 2;" ::: "memory");
}

// SW64 swizzle term for a 64B row
__device__ __forceinline__ uint32_t srow(int row) { return ((row >> 1) & 3) << 4; }

// ---------------------------------------------------------------------------
// elementwise fp32 -> bf16 hi/lo split
// ---------------------------------------------------------------------------
__global__ void __launch_bounds__(256)
split_kernel(const float* __restrict__ src, uint16_t* __restrict__ hi,
             uint16_t* __restrict__ lo, long n4)
{
    long i = (long)blockIdx.x * 256 + threadIdx.x;
    if (i >= n4) return;
    float4 v = ((const float4*)src)[i];
    uint32_t h0, l0, h1, l1;
    split2(v.x, v.y, h0, l0);
    split2(v.z, v.w, h1, l1);
    ((uint2*)hi)[i] = make_uint2(h0, h1);
    ((uint2*)lo)[i] = make_uint2(l0, l1);
}

// ---------------------------------------------------------------------------
// TN GEMM, bf16 hi/lo inputs, fp32 accum. CTA 128x256, warp 64x64.
// A: [M,K] lda ; B: [N,K] ldb ; C: [M,N] ldc ; batch via blockIdx.z strides.
// BIAS: 0 none, 1 bias[col], 2 bias[row].
// CAUSAL: mask col>row -inf + skip tiles fully above diagonal (fp32 out only).
// KLIM: K loop to bm0+BM. SPLIT: write bf16 hi/lo C, else fp32.
// ---------------------------------------------------------------------------
template <int BIAS, bool CAUSAL, bool KLIM, bool SPLIT>
__global__ void __launch_bounds__(NT, 1)
mm(const uint16_t* __restrict__ Agh, const uint16_t* __restrict__ Agl,
   const uint16_t* __restrict__ Bgh, const uint16_t* __restrict__ Bgl,
   const float* __restrict__ bias, float* __restrict__ Cf,
   uint16_t* __restrict__ Ch, uint16_t* __restrict__ Cl,
   int K, int lda, int ldb, int ldc, float scale,
   long sA, long sB, long sC)
{
    const int bm0 = blockIdx.y * BM;
    const int bn0 = blockIdx.x * BN;
    const int tid = threadIdx.x;
    const int lane = tid & 31;
    const int wid = tid >> 5;

    Agh += (long)blockIdx.z * sA;  Agl += (long)blockIdx.z * sA;
    Bgh += (long)blockIdx.z * sB;  Bgl += (long)blockIdx.z * sB;
    const long czoff = (long)blockIdx.z * sC;

    if (CAUSAL && bn0 >= bm0 + BM) {
        // Entire tile strictly above diagonal: -inf fill, skip compute.
        float* C = Cf + czoff;
        const float2 mi = make_float2(-INFINITY, -INFINITY);
        for (int i = tid; i < 128 * 128; i += NT) {
            const int r = i >> 7;
            const int c = (i & 127) * 2;
            *(float2*)(C + (long)(bm0 + r) * ldc + bn0 + c) = mi;
        }
        return;
    }

    extern __shared__ char smem[];
    const uint32_t sb0 = smem_u32(smem);

    // ---- loader mapping (12 cp16/thread): lr = tid>>2, lc = tid&3 ----
    const int lr = tid >> 2;             // 0..63
    const int lc = tid & 3;              // 16B chunk within 64B row
    const uint32_t swA0 = (lr      ) * 64 + ((lc << 4) ^ srow(lr));
    const uint32_t swA1 = (lr +  64) * 64 + ((lc << 4) ^ srow(lr + 64));
    const uint32_t swB0 = swA0;
    const uint32_t swB1 = swA1;
    const uint32_t swB2 = (lr + 128) * 64 + ((lc << 4) ^ srow(lr + 128));
    const uint32_t swB3 = (lr + 192) * 64 + ((lc << 4) ^ srow(lr + 192));
    const uint16_t* A0h = Agh + (long)(bm0 + lr      ) * lda + lc * 8;
    const uint16_t* A1h = Agh + (long)(bm0 + lr +  64) * lda + lc * 8;
    const uint16_t* A0l = Agl + (long)(bm0 + lr      ) * lda + lc * 8;
    const uint16_t* A1l = Agl + (long)(bm0 + lr +  64) * lda + lc * 8;
    const uint16_t* B0h = Bgh + (long)(bn0 + lr      ) * ldb + lc * 8;
    const uint16_t* B1h = Bgh + (long)(bn0 + lr +  64) * ldb + lc * 8;
    const uint16_t* B2h = Bgh + (long)(bn0 + lr + 128) * ldb + lc * 8;
    const uint16_t* B3h = Bgh + (long)(bn0 + lr + 192) * ldb + lc * 8;
    const uint16_t* B0l = Bgl + (long)(bn0 + lr      ) * ldb + lc * 8;
    const uint16_t* B1l = Bgl + (long)(bn0 + lr +  64) * ldb + lc * 8;
    const uint16_t* B2l = Bgl + (long)(bn0 + lr + 128) * ldb + lc * 8;
    const uint16_t* B3l = Bgl + (long)(bn0 + lr + 192) * ldb + lc * 8;

    auto issue = [&](int stg, int k0) {
        const uint32_t sb = sb0 + stg * STAGE_BYTES;
        cp16(sb          + swA0, A0h + k0);
        cp16(sb          + swA1, A1h + k0);
        cp16(sb + OFF_AL + swA0, A0l + k0);
        cp16(sb + OFF_AL + swA1, A1l + k0);
        cp16(sb + OFF_BH + swB0, B0h + k0);
        cp16(sb + OFF_BH + swB1, B1h + k0);
        cp16(sb + OFF_BH + swB2, B2h + k0);
        cp16(sb + OFF_BH + swB3, B3h + k0);
        cp16(sb + OFF_BL + swB0, B0l + k0);
        cp16(sb + OFF_BL + swB1, B1l + k0);
        cp16(sb + OFF_BL + swB2, B2l + k0);
        cp16(sb + OFF_BL + swB3, B3l + k0);
    };

    // ---- ldmatrix address precompute ----
    // warp tile 64(M) x 64(N): m0 = (wid&1)*64, n0 = (wid>>1)*64
    const int m0 = (wid & 1) * 64;
    const int n0 = (wid >> 1) * 64;
    const int fr = (lane & 7) + ((lane >> 3) & 1) * 8;
    const int cb = (lane >> 4) & 1;
    uint32_t aoff[4][2], boff[4][2];
    #pragma unroll
    for (int mt = 0; mt < 4; ++mt) {
        const int row = m0 + mt * 16 + fr;
        const uint32_t s = srow(row);
        aoff[mt][0] = row * 64 + (((0 + cb) << 4) ^ s);
        aoff[mt][1] = row * 64 + (((2 + cb) << 4) ^ s);
    }
    #pragma unroll
    for (int n4 = 0; n4 < 4; ++n4) {
        const int row = n0 + n4 * 16 + fr;
        const uint32_t s = srow(row);
        boff[n4][0] = row * 64 + (((0 + cb) << 4) ^ s);
        boff[n4][1] = row * 64 + (((2 + cb) << 4) ^ s);
    }

    float acc[4][8][4] = {};

    const int kend  = KLIM ? (bm0 + BM) : K;
    const int niter = kend / BK;           // >= 4 always here

    issue(0, 0);          cp_commit();
    issue(1, BK);         cp_commit();
    issue(2, 2 * BK);     cp_commit();

    for (int it = 0; it < niter; ++it) {
        cp_wait2();
        __syncthreads();
        const int nx = it + 3;
        if (nx < niter) issue(nx % STAGES, nx * BK);   // (it+3)%4 != it%4: safe
        cp_commit();

        const uint32_t sb = sb0 + (it % STAGES) * STAGE_BYTES;

        #pragma unroll
        for (int ks = 0; ks < 2; ++ks) {
            uint32_t ahf[4][4], alf[4][4], bhf[4][4], blf[4][4];
            #pragma unroll
            for (int mt = 0; mt < 4; ++mt) {
                ldsm4(ahf[mt], sb + aoff[mt][ks]);
                ldsm4(alf[mt], sb + OFF_AL + aoff[mt][ks]);
            }
            #pragma unroll
            for (int n4 = 0; n4 < 4; ++n4) {
                ldsm4(bhf[n4], sb + OFF_BH + boff[n4][ks]);
                ldsm4(blf[n4], sb + OFF_BL + boff[n4][ks]);
            }
            // pass 1: Alo * Bhi
            #pragma unroll
            for (int nt = 0; nt < 8; ++nt) {
                const int n4 = nt >> 1, sl = nt & 1;
                const uint32_t b0 = bhf[n4][sl], b1 = bhf[n4][2 + sl];
                #pragma unroll
                for (int mt = 0; mt < 4; ++mt)
                    mma_bf16(acc[mt][nt], alf[mt], b0, b1);
            }
            // pass 2: Ahi * Blo
            #pragma unroll
            for (int nt = 0; nt < 8; ++nt) {
                const int n4 = nt >> 1, sl = nt & 1;
                const uint32_t b0 = blf[n4][sl], b1 = blf[n4][2 + sl];
                #pragma unroll
                for (int mt = 0; mt < 4; ++mt)
                    mma_bf16(acc[mt][nt], ahf[mt], b0, b1);
            }
            // pass 3: Ahi * Bhi
            #pragma unroll
            for (int nt = 0; nt < 8; ++nt) {
                const int n4 = nt >> 1, sl = nt & 1;
                const uint32_t b0 = bhf[n4][sl], b1 = bhf[n4][2 + sl];
                #pragma unroll
                for (int mt = 0; mt < 4; ++mt)
                    mma_bf16(acc[mt][nt], ahf[mt], b0, b1);
            }
        }
    }

    // ---- epilogue ----
    const int g  = lane >> 2;
    const int tg = lane & 3;
    #pragma unroll
    for (int mt = 0; mt < 4; ++mt)
        #pragma unroll
        for (int nt = 0; nt < 8; ++nt) {
            const int r = bm0 + m0 + mt * 16 + g;
            const int c = bn0 + n0 + nt * 8 + tg * 2;
            float v0 = acc[mt][nt][0] * scale;
            float v1 = acc[mt][nt][1] * scale;
            float v2 = acc[mt][nt][2] * scale;
            float v3 = acc[mt][nt][3] * scale;
            if (BIAS == 1) {
                const float b0 = bias[c], b1 = bias[c + 1];
                v0 += b0; v1 += b1; v2 += b0; v3 += b1;
            }
            if (BIAS == 2) {
                const float br0 = bias[r], br1 = bias[r + 8];
                v0 += br0; v1 += br0; v2 += br1; v3 += br1;
            }
            if (SPLIT) {
                uint16_t* ch = Ch + czoff;
                uint16_t* cl = Cl + czoff;
                uint32_t h, l;
                split2(v0, v1, h, l);
                *(uint32_t*)(ch + (long)r * ldc + c) = h;
                *(uint32_t*)(cl + (long)r * ldc + c) = l;
                split2(v2, v3, h, l);
                *(uint32_t*)(ch + (long)(r + 8) * ldc + c) = h;
                *(uint32_t*)(cl + (long)(r + 8) * ldc + c) = l;
            } else {
                if (CAUSAL) {
                    if (c > r)         v0 = -INFINITY;
                    if (c + 1 > r)     v1 = -INFINITY;
                    if (c > r + 8)     v2 = -INFINITY;
                    if (c + 1 > r + 8) v3 = -INFINITY;
                }
                float* C = Cf + czoff;
                *(float2*)(C + (long)r * ldc + c) = make_float2(v0, v1);
                *(float2*)(C + (long)(r + 8) * ldc + c) = make_float2(v2, v3);
            }
        }
}

// ---------------------------------------------------------------------------
// Row softmax over 2048 cols; writes attn as bf16 hi/lo. One block per row.
// ---------------------------------------------------------------------------
__global__ void __launch_bounds__(256)
softmax_split(const float* __restrict__ S, uint16_t* __restrict__ Ah,
              uint16_t* __restrict__ Al)
{
    const long row = blockIdx.x;
    const float* p = S + row * 2048L;
    const int tid = threadIdx.x;

    float4 va = ((const float4*)p)[tid * 2];
    float4 vb = ((const float4*)p)[tid * 2 + 1];
    float v[8] = {va.x, va.y, va.z, va.w, vb.x, vb.y, vb.z, vb.w};

    float m = -INFINITY;
    #pragma unroll
    for (int i = 0; i < 8; ++i) m = fmaxf(m, v[i]);
    #pragma unroll
    for (int o = 16; o > 0; o >>= 1)
        m = fmaxf(m, __shfl_xor_sync(0xffffffffu, m, o));

    __shared__ float red[8];
    if ((tid & 31) == 0) red[tid >> 5] = m;
    __syncthreads();
    float mg = red[0];
    #pragma unroll
    for (int w = 1; w < 8; ++w) mg = fmaxf(mg, red[w]);

    float sum = 0.0f;
    #pragma unroll
    for (int i = 0; i < 8; ++i) {
        v[i] = __expf(v[i] - mg);
        sum += v[i];
    }
    #pragma unroll
    for (int o = 16; o > 0; o >>= 1)
        sum += __shfl_xor_sync(0xffffffffu, sum, o);
    __syncthreads();
    if ((tid & 31) == 0) red[tid >> 5] = sum;
    __syncthreads();
    float tot = 0.0f;
    #pragma unroll
    for (int w = 0; w < 8; ++w) tot += red[w];
    const float inv = 1.0f / tot;

    uint32_t* oh = (uint32_t*)(Ah + row * 2048L) + tid * 4;
    uint32_t* ol = (uint32_t*)(Al + row * 2048L) + tid * 4;
    #pragma unroll
    for (int j = 0; j < 4; ++j) {
        uint32_t h, l;
        split2(v[2 * j] * inv, v[2 * j + 1] * inv, h, l);
        oh[j] = h;
        ol[j] = l;
    }
}

// ---------------------------------------------------------------------------
// Launch
// ---------------------------------------------------------------------------
extern "C" void kernel_launch(void* const* d_in, const int* in_sizes, int n_in,
                              void* d_out, int out_size)
{
    const float* x  = (const float*)d_in[0];
    // d_in[1] is the causal tril mask -> applied analytically.
    const float* Wq = (const float*)d_in[2];
    const float* bq = (const float*)d_in[3];
    const float* Wk = (const float*)d_in[4];
    const float* bk = (const float*)d_in[5];
    const float* Wv = (const float*)d_in[6];
    const float* bv = (const float*)d_in[7];
    const float* Wp = (const float*)d_in[8];
    const float* bp = (const float*)d_in[9];
    float* out = (float*)d_out;

    uint8_t* pool;
    cudaGetSymbolAddress((void**)&pool, g_pool);

    // pool carving (liveness-based reuse)
    uint16_t* xh  = (uint16_t*)(pool + 0 * UNIT);
    uint16_t* xl  = (uint16_t*)(pool + 1 * UNIT);
    uint16_t* qh  = (uint16_t*)(pool + 2 * UNIT);
    uint16_t* ql  = (uint16_t*)(pool + 3 * UNIT);
    uint16_t* kh  = (uint16_t*)(pool + 4 * UNIT);
    uint16_t* kl  = (uint16_t*)(pool + 5 * UNIT);
    uint16_t* vth = (uint16_t*)(pool + 6 * UNIT);
    uint16_t* vtl = (uint16_t*)(pool + 7 * UNIT);
    uint16_t* wh  = (uint16_t*)(pool + 8 * UNIT);
    uint16_t* wl  = (uint16_t*)(pool + 8 * UNIT + WUNIT);
    float*    s   = (float*)   (pool + 0 * UNIT);   // reuses x (dead)
    uint16_t* ah  = qh;                             // attn reuses q (dead)
    uint16_t* al  = ql;
    uint16_t* ch  = kh;                             // ctx reuses k (dead)
    uint16_t* cl  = kl;

    cudaFuncSetAttribute(mm<1, false, false, true>,
                         cudaFuncAttributeMaxDynamicSharedMemorySize, SMEM_TOTAL);
    cudaFuncSetAttribute(mm<2, false, false, true>,
                         cudaFuncAttributeMaxDynamicSharedMemorySize, SMEM_TOTAL);
    cudaFuncSetAttribute(mm<0, true, false, false>,
                         cudaFuncAttributeMaxDynamicSharedMemorySize, SMEM_TOTAL);
    cudaFuncSetAttribute(mm<0, false, true, true>,
                         cudaFuncAttributeMaxDynamicSharedMemorySize, SMEM_TOTAL);
    cudaFuncSetAttribute(mm<1, false, false, false>,
                         cudaFuncAttributeMaxDynamicSharedMemorySize, SMEM_TOTAL);

    const int Bt = 4, S2 = 2048, D = 2048;
    const int Mtot = Bt * S2;                  // 8192
    const long ts = (long)S2 * D;              // token-batch stride (elements)
    const long bs = (long)S2 * S2;             // scores batch stride
    const long wsz = (long)D * D;
    const float inv_std = 1.0f / sqrtf((float)D);

    dim3 blk(NT);
    dim3 gproj(D / BN, Mtot / BM, 1);          // (8, 64)
    dim3 gvt(Mtot / BN, D / BM, 1);            // (32, 16)
    dim3 gattn(S2 / BN, S2 / BM, Bt);          // (8, 16, 4)
    const unsigned gsx  = (unsigned)(ts * Bt / 4 / 256);
    const unsigned gsw  = (unsigned)(wsz / 4 / 256);

    // x split (used by q, k, vt)
    split_kernel<<<gsx, 256>>>(x, xh, xl, ts * Bt / 4);

    // q = x @ Wq^T + bq
    split_kernel<<<gsw, 256>>>(Wq, wh, wl, wsz / 4);
    mm<1, false, false, true><<<gproj, blk, SMEM_TOTAL>>>(
        xh, xl, wh, wl, bq, nullptr, qh, ql, D, D, D, D, 1.0f, 0, 0, 0);

    // k = x @ Wk^T + bk
    split_kernel<<<gsw, 256>>>(Wk, wh, wl, wsz / 4);
    mm<1, false, false, true><<<gproj, blk, SMEM_TOTAL>>>(
        xh, xl, wh, wl, bk, nullptr, kh, kl, D, D, D, D, 1.0f, 0, 0, 0);

    // vt[d,t] = sum_e Wv[d,e] x[t,e] + bv[d]  (V transposed, row bias)
    split_kernel<<<gsw, 256>>>(Wv, wh, wl, wsz / 4);
    mm<2, false, false, true><<<gvt, blk, SMEM_TOTAL>>>(
        wh, wl, xh, xl, bv, nullptr, vth, vtl, D, D, D, Mtot, 1.0f, 0, 0, 0);

    // scores = (q @ k^T) * inv_std, causal, fp32 out (into x's region; x dead)
    mm<0, true, false, false><<<gattn, blk, SMEM_TOTAL>>>(
        qh, ql, kh, kl, nullptr, s, nullptr, nullptr,
        D, D, D, S2, inv_std, ts, ts, bs);

    // softmax rows -> attn hi/lo (into q's region; q dead)
    softmax_split<<<Bt * S2, 256>>>(s, ah, al);

    // ctx[q,d] = sum_k attn[q,k] vt[d, z*S2+k]  (K-limited; into k's region)
    mm<0, false, true, true><<<gattn, blk, SMEM_TOTAL>>>(
        ah, al, vth, vtl, nullptr, nullptr, ch, cl,
        S2, S2, Mtot, D, 1.0f, bs, S2, ts);

    // out = ctx @ Wp^T + bp  (fp32 out)
    split_kernel<<<gsw, 256>>>(Wp, wh, wl, wsz / 4);
    mm<1, false, false, false><<<gproj, blk, SMEM_TOTAL>>>(
        ch, cl, wh, wl, bp, out, nullptr, nullptr, D, D, D, D, 1.0f, 0, 0, 0);
}

// round 17
// speedup vs baseline: 1.1368x; 1.1368x over previous
#include <cuda_runtime.h>
#include <cuda_bf16.h>
#include <math.h>
#include <stdint.h>

// ---------------------------------------------------------------------------
// Attention_51977694216863 (B=4, S=2048, D=2048, fp32).
// mma.sync bf16x3 pipeline, CTA 128x128, warp 32x64 — round-11 proven config.
// Round-17 change: __launch_bounds__(256, 2) -> 2 CTAs/SM (4 warps/SMSP).
// Round-5 evidence (occ=12.5%, issue=21.8%) says the GEMM is latency-bound at
// 2 warps/SMSP; ordering (r12) and tile width (r16) were both non-fixes.
// C = scale*(A @ B^T)[+bias][causal|K-limit]; D += Alo*Bhi + Ahi*Blo + Ahi*Bhi
// ---------------------------------------------------------------------------

#define BM 128
#define BN 128
#define BK 32
#define NT 256
#define STAGES 3
#define PART_BYTES  8192                   // 128 rows x 32 bf16 x 2B
#define STAGE_BYTES (4 * PART_BYTES)       // Ah, Al, Bh, Bl = 32768
#define SMEM_TOTAL  (STAGES * STAGE_BYTES) // 98304 B/CTA -> 192KB for 2 CTAs

// ---------------------------------------------------------------------------
// Pooled scratch (allocation-free rule: one __device__ global), 285MB peak.
//   [0,2U): xh,xl -> later fp32 scores s   [2U,4U): qh,ql -> attn hi/lo
//   [4U,6U): kh,kl -> ctx hi/lo            [6U,8U): vth,vtl
//   [8U,+2W): wh,wl (re-split per projection)
// ---------------------------------------------------------------------------
#define UNIT (8192L * 2048 * 2)
#define WUNIT (2048L * 2048 * 2)
__device__ __align__(256) uint8_t g_pool[8 * UNIT + 2 * WUNIT];

// ---------------------------------------------------------------------------
// helpers
// ---------------------------------------------------------------------------
__device__ __forceinline__ uint32_t smem_u32(const void* p) {
    uint32_t a;
    asm("{ .reg .u64 t; cvta.to.shared.u64 t, %1; cvt.u32.u64 %0, t; }"
        : "=r"(a) : "l"(p));
    return a;
}

__device__ __forceinline__ uint32_t cvt_bf16x2(float lo_e, float hi_e) {
    uint32_t r;
    asm("cvt.rn.bf16x2.f32 %0, %1, %2;" : "=r"(r) : "f"(hi_e), "f"(lo_e));
    return r;  // low half = lo_e, high half = hi_e
}
__device__ __forceinline__ void split2(float e0, float e1, uint32_t& hi, uint32_t& lo) {
    uint32_t h = cvt_bf16x2(e0, e1);
    float f0 = __uint_as_float(h << 16);
    float f1 = __uint_as_float(h & 0xffff0000u);
    lo = cvt_bf16x2(e0 - f0, e1 - f1);
    hi = h;
}

__device__ __forceinline__ void mma_bf16(float* c, const uint32_t* a,
                                         uint32_t b0, uint32_t b1) {
    asm volatile(
        "mma.sync.aligned.m16n8k16.row.col.f32.bf16.bf16.f32 "
        "{%0,%1,%2,%3}, {%4,%5,%6,%7}, {%8,%9}, {%0,%1,%2,%3};"
        : "+f"(c[0]), "+f"(c[1]), "+f"(c[2]), "+f"(c[3])
        : "r"(a[0]), "r"(a[1]), "r"(a[2]), "r"(a[3]), "r"(b0), "r"(b1));
}

__device__ __forceinline__ void ldsm4(uint32_t* r, uint32_t addr) {
    asm volatile("ldmatrix.sync.aligned.m8n8.x4.shared.b16 {%0,%1,%2,%3}, [%4];"
                 : "=r"(r[0]), "=r"(r[1]), "=r"(r[2]), "=r"(r[3]) : "r"(addr));
}

__device__ __forceinline__ void cp16(uint32_t dst, const void* src) {
    asm volatile("cp.async.cg.shared.global [%0], [%1], 16;"
                 :: "r"(dst), "l"(src));
}
__device__ __forceinline__ void cp_commit() {
    asm volatile("cp.async.commit_group;" ::: "memory");
}
__device__ __forceinline__ void cp_wait1() {
    asm volatile("cp.async.wait_group 1;" ::: "memory");
}

// SW64 swizzle term for a 64B row
__device__ __forceinline__ uint32_t srow(int row) { return ((row >> 1) & 3) << 4; }

// ---------------------------------------------------------------------------
// elementwise fp32 -> bf16 hi/lo split
// ---------------------------------------------------------------------------
__global__ void __launch_bounds__(256)
split_kernel(const float* __restrict__ src, uint16_t* __restrict__ hi,
             uint16_t* __restrict__ lo, long n4)
{
    long i = (long)blockIdx.x * 256 + threadIdx.x;
    if (i >= n4) return;
    float4 v = ((const float4*)src)[i];
    uint32_t h0, l0, h1, l1;
    split2(v.x, v.y, h0, l0);
    split2(v.z, v.w, h1, l1);
    ((uint2*)hi)[i] = make_uint2(h0, h1);
    ((uint2*)lo)[i] = make_uint2(l0, l1);
}

// ---------------------------------------------------------------------------
// TN GEMM, bf16 hi/lo inputs, fp32 accum. CTA 128x128, warp 32x64, 2 CTAs/SM.
// A: [M,K] lda ; B: [N,K] ldb ; C: [M,N] ldc ; batch via blockIdx.z strides.
// BIAS: 0 none, 1 bias[col], 2 bias[row].
// CAUSAL: mask col>row -inf + skip tiles fully above diagonal (fp32 out only).
// KLIM: K loop to bm0+BM. SPLIT: write bf16 hi/lo C, else fp32.
// ---------------------------------------------------------------------------
template <int BIAS, bool CAUSAL, bool KLIM, bool SPLIT>
__global__ void __launch_bounds__(NT, 2)
mm(const uint16_t* __restrict__ Agh, const uint16_t* __restrict__ Agl,
   const uint16_t* __restrict__ Bgh, const uint16_t* __restrict__ Bgl,
   const float* __restrict__ bias, float* __restrict__ Cf,
   uint16_t* __restrict__ Ch, uint16_t* __restrict__ Cl,
   int K, int lda, int ldb, int ldc, float scale,
   long sA, long sB, long sC)
{
    const int bm0 = blockIdx.y * BM;
    const int bn0 = blockIdx.x * BN;
    const int tid = threadIdx.x;
    const int lane = tid & 31;
    const int wid = tid >> 5;

    Agh += (long)blockIdx.z * sA;  Agl += (long)blockIdx.z * sA;
    Bgh += (long)blockIdx.z * sB;  Bgl += (long)blockIdx.z * sB;
    const long czoff = (long)blockIdx.z * sC;

    if (CAUSAL && bn0 >= bm0 + BM) {
        // Entire tile strictly above diagonal: -inf fill, skip compute.
        float* C = Cf + czoff;
        const float2 mi = make_float2(-INFINITY, -INFINITY);
        for (int i = tid; i < 128 * 64; i += NT) {
            const int r = i >> 6;
            const int c = (i & 63) * 2;
            *(float2*)(C + (long)(bm0 + r) * ldc + bn0 + c) = mi;
        }
        return;
    }

    extern __shared__ char smem[];
    const uint32_t sb0 = smem_u32(smem);

    // ---- loader mapping: thread t covers one 16B chunk of 2 rows per part ----
    const int lr0 = tid >> 2;            // rows 0..63
    const int lr1 = lr0 + 64;            // rows 64..127
    const int lc  = tid & 3;             // 16B chunk within 64B row
    const uint32_t sw0 = lr0 * 64 + ((lc << 4) ^ srow(lr0));
    const uint32_t sw1 = lr1 * 64 + ((lc << 4) ^ srow(lr1));
    const uint16_t* A0h = Agh + (long)(bm0 + lr0) * lda + lc * 8;
    const uint16_t* A1h = Agh + (long)(bm0 + lr1) * lda + lc * 8;
    const uint16_t* A0l = Agl + (long)(bm0 + lr0) * lda + lc * 8;
    const uint16_t* A1l = Agl + (long)(bm0 + lr1) * lda + lc * 8;
    const uint16_t* B0h = Bgh + (long)(bn0 + lr0) * ldb + lc * 8;
    const uint16_t* B1h = Bgh + (long)(bn0 + lr1) * ldb + lc * 8;
    const uint16_t* B0l = Bgl + (long)(bn0 + lr0) * ldb + lc * 8;
    const uint16_t* B1l = Bgl + (long)(bn0 + lr1) * ldb + lc * 8;

    auto issue = [&](int stg, int k0) {
        const uint32_t sb = sb0 + stg * STAGE_BYTES;
        cp16(sb                  + sw0, A0h + k0);
        cp16(sb                  + sw1, A1h + k0);
        cp16(sb +     PART_BYTES + sw0, A0l + k0);
        cp16(sb +     PART_BYTES + sw1, A1l + k0);
        cp16(sb + 2 * PART_BYTES + sw0, B0h + k0);
        cp16(sb + 2 * PART_BYTES + sw1, B1h + k0);
        cp16(sb + 3 * PART_BYTES + sw0, B0l + k0);
        cp16(sb + 3 * PART_BYTES + sw1, B1l + k0);
    };

    // ---- ldmatrix address precompute ----
    // warp tile: 32(M) x 64(N); fr = row-in-16, cb = k-chunk parity
    const int m0 = (wid & 3) * 32;
    const int n0 = (wid >> 2) * 64;
    const int fr = (lane & 7) + ((lane >> 3) & 1) * 8;
    const int cb = (lane >> 4) & 1;
    uint32_t aoff[2][2], boff[4][2];
    #pragma unroll
    for (int mt = 0; mt < 2; ++mt) {
        const int row = m0 + mt * 16 + fr;
        const uint32_t s = srow(row);
        aoff[mt][0] = row * 64 + (((0 + cb) << 4) ^ s);
        aoff[mt][1] = row * 64 + (((2 + cb) << 4) ^ s);
    }
    #pragma unroll
    for (int n4 = 0; n4 < 4; ++n4) {
        const int row = n0 + n4 * 16 + fr;
        const uint32_t s = srow(row);
        boff[n4][0] = row * 64 + (((0 + cb) << 4) ^ s);
        boff[n4][1] = row * 64 + (((2 + cb) << 4) ^ s);
    }

    float acc[2][8][4] = {};

    const int kend  = KLIM ? (bm0 + BM) : K;
    const int niter = kend / BK;           // >= 4 always here

    issue(0, 0);      cp_commit();
    issue(1, BK);     cp_commit();

    for (int it = 0; it < niter; ++it) {
        cp_wait1();
        __syncthreads();
        const int nx = it + 2;
        if (nx < niter) issue(nx % STAGES, nx * BK);   // (it+2)%3 != it%3: safe
        cp_commit();

        const uint32_t sb = sb0 + (it % STAGES) * STAGE_BYTES;

        #pragma unroll
        for (int ks = 0; ks < 2; ++ks) {
            uint32_t ahf[2][4], alf[2][4], bhf[4][4], blf[4][4];
            #pragma unroll
            for (int mt = 0; mt < 2; ++mt) {
                ldsm4(ahf[mt], sb + aoff[mt][ks]);
                ldsm4(alf[mt], sb + PART_BYTES + aoff[mt][ks]);
            }
            #pragma unroll
            for (int n4 = 0; n4 < 4; ++n4) {
                ldsm4(bhf[n4], sb + 2 * PART_BYTES + boff[n4][ks]);
                ldsm4(blf[n4], sb + 3 * PART_BYTES + boff[n4][ks]);
            }
            // pass 1: Alo * Bhi
            #pragma unroll
            for (int nt = 0; nt < 8; ++nt) {
                const int n4 = nt >> 1, sl = nt & 1;
                const uint32_t b0 = bhf[n4][sl], b1 = bhf[n4][2 + sl];
                #pragma unroll
                for (int mt = 0; mt < 2; ++mt)
                    mma_bf16(acc[mt][nt], alf[mt], b0, b1);
            }
            // pass 2: Ahi * Blo
            #pragma unroll
            for (int nt = 0; nt < 8; ++nt) {
                const int n4 = nt >> 1, sl = nt & 1;
                const uint32_t b0 = blf[n4][sl], b1 = blf[n4][2 + sl];
                #pragma unroll
                for (int mt = 0; mt < 2; ++mt)
                    mma_bf16(acc[mt][nt], ahf[mt], b0, b1);
            }
            // pass 3: Ahi * Bhi
            #pragma unroll
            for (int nt = 0; nt < 8; ++nt) {
                const int n4 = nt >> 1, sl = nt & 1;
                const uint32_t b0 = bhf[n4][sl], b1 = bhf[n4][2 + sl];
                #pragma unroll
                for (int mt = 0; mt < 2; ++mt)
                    mma_bf16(acc[mt][nt], ahf[mt], b0, b1);
            }
        }
    }

    // ---- epilogue ----
    const int g  = lane >> 2;
    const int tg = lane & 3;
    #pragma unroll
    for (int mt = 0; mt < 2; ++mt)
        #pragma unroll
        for (int nt = 0; nt < 8; ++nt) {
            const int r = bm0 + m0 + mt * 16 + g;
            const int c = bn0 + n0 + nt * 8 + tg * 2;
            float v0 = acc[mt][nt][0] * scale;
            float v1 = acc[mt][nt][1] * scale;
            float v2 = acc[mt][nt][2] * scale;
            float v3 = acc[mt][nt][3] * scale;
            if (BIAS == 1) {
                const float b0 = bias[c], b1 = bias[c + 1];
                v0 += b0; v1 += b1; v2 += b0; v3 += b1;
            }
            if (BIAS == 2) {
                const float br0 = bias[r], br1 = bias[r + 8];
                v0 += br0; v1 += br0; v2 += br1; v3 += br1;
            }
            if (SPLIT) {
                uint16_t* ch = Ch + czoff;
                uint16_t* cl = Cl + czoff;
                uint32_t h, l;
                split2(v0, v1, h, l);
                *(uint32_t*)(ch + (long)r * ldc + c) = h;
                *(uint32_t*)(cl + (long)r * ldc + c) = l;
                split2(v2, v3, h, l);
                *(uint32_t*)(ch + (long)(r + 8) * ldc + c) = h;
                *(uint32_t*)(cl + (long)(r + 8) * ldc + c) = l;
            } else {
                if (CAUSAL) {
                    if (c > r)         v0 = -INFINITY;
                    if (c + 1 > r)     v1 = -INFINITY;
                    if (c > r + 8)     v2 = -INFINITY;
                    if (c + 1 > r + 8) v3 = -INFINITY;
                }
                float* C = Cf + czoff;
                *(float2*)(C + (long)r * ldc + c) = make_float2(v0, v1);
                *(float2*)(C + (long)(r + 8) * ldc + c) = make_float2(v2, v3);
            }
        }
}

// ---------------------------------------------------------------------------
// Row softmax over 2048 cols; writes attn as bf16 hi/lo. One block per row.
// ---------------------------------------------------------------------------
__global__ void __launch_bounds__(256)
softmax_split(const float* __restrict__ S, uint16_t* __restrict__ Ah,
              uint16_t* __restrict__ Al)
{
    const long row = blockIdx.x;
    const float* p = S + row * 2048L;
    const int tid = threadIdx.x;

    float4 va = ((const float4*)p)[tid * 2];
    float4 vb = ((const float4*)p)[tid * 2 + 1];
    float v[8] = {va.x, va.y, va.z, va.w, vb.x, vb.y, vb.z, vb.w};

    float m = -INFINITY;
    #pragma unroll
    for (int i = 0; i < 8; ++i) m = fmaxf(m, v[i]);
    #pragma unroll
    for (int o = 16; o > 0; o >>= 1)
        m = fmaxf(m, __shfl_xor_sync(0xffffffffu, m, o));

    __shared__ float red[8];
    if ((tid & 31) == 0) red[tid >> 5] = m;
    __syncthreads();
    float mg = red[0];
    #pragma unroll
    for (int w = 1; w < 8; ++w) mg = fmaxf(mg, red[w]);

    float sum = 0.0f;
    #pragma unroll
    for (int i = 0; i < 8; ++i) {
        v[i] = __expf(v[i] - mg);
        sum += v[i];
    }
    #pragma unroll
    for (int o = 16; o > 0; o >>= 1)
        sum += __shfl_xor_sync(0xffffffffu, sum, o);
    __syncthreads();
    if ((tid & 31) == 0) red[tid >> 5] = sum;
    __syncthreads();
    float tot = 0.0f;
    #pragma unroll
    for (int w = 0; w < 8; ++w) tot += red[w];
    const float inv = 1.0f / tot;

    uint32_t* oh = (uint32_t*)(Ah + row * 2048L) + tid * 4;
    uint32_t* ol = (uint32_t*)(Al + row * 2048L) + tid * 4;
    #pragma unroll
    for (int j = 0; j < 4; ++j) {
        uint32_t h, l;
        split2(v[2 * j] * inv, v[2 * j + 1] * inv, h, l);
        oh[j] = h;
        ol[j] = l;
    }
}

// ---------------------------------------------------------------------------
// Launch
// ---------------------------------------------------------------------------
extern "C" void kernel_launch(void* const* d_in, const int* in_sizes, int n_in,
                              void* d_out, int out_size)
{
    const float* x  = (const float*)d_in[0];
    // d_in[1] is the causal tril mask -> applied analytically.
    const float* Wq = (const float*)d_in[2];
    const float* bq = (const float*)d_in[3];
    const float* Wk = (const float*)d_in[4];
    const float* bk = (const float*)d_in[5];
    const float* Wv = (const float*)d_in[6];
    const float* bv = (const float*)d_in[7];
    const float* Wp = (const float*)d_in[8];
    const float* bp = (const float*)d_in[9];
    float* out = (float*)d_out;

    uint8_t* pool;
    cudaGetSymbolAddress((void**)&pool, g_pool);

    // pool carving (liveness-based reuse)
    uint16_t* xh  = (uint16_t*)(pool + 0 * UNIT);
    uint16_t* xl  = (uint16_t*)(pool + 1 * UNIT);
    uint16_t* qh  = (uint16_t*)(pool + 2 * UNIT);
    uint16_t* ql  = (uint16_t*)(pool + 3 * UNIT);
    uint16_t* kh  = (uint16_t*)(pool + 4 * UNIT);
    uint16_t* kl  = (uint16_t*)(pool + 5 * UNIT);
    uint16_t* vth = (uint16_t*)(pool + 6 * UNIT);
    uint16_t* vtl = (uint16_t*)(pool + 7 * UNIT);
    uint16_t* wh  = (uint16_t*)(pool + 8 * UNIT);
    uint16_t* wl  = (uint16_t*)(pool + 8 * UNIT + WUNIT);
    float*    s   = (float*)   (pool + 0 * UNIT);   // reuses x (dead)
    uint16_t* ah  = qh;                             // attn reuses q (dead)
    uint16_t* al  = ql;
    uint16_t* ch  = kh;                             // ctx reuses k (dead)
    uint16_t* cl  = kl;

    cudaFuncSetAttribute(mm<1, false, false, true>,
                         cudaFuncAttributeMaxDynamicSharedMemorySize, SMEM_TOTAL);
    cudaFuncSetAttribute(mm<2, false, false, true>,
                         cudaFuncAttributeMaxDynamicSharedMemorySize, SMEM_TOTAL);
    cudaFuncSetAttribute(mm<0, true, false, false>,
                         cudaFuncAttributeMaxDynamicSharedMemorySize, SMEM_TOTAL);
    cudaFuncSetAttribute(mm<0, false, true, true>,
                         cudaFuncAttributeMaxDynamicSharedMemorySize, SMEM_TOTAL);
    cudaFuncSetAttribute(mm<1, false, false, false>,
                         cudaFuncAttributeMaxDynamicSharedMemorySize, SMEM_TOTAL);

    const int Bt = 4, S2 = 2048, D = 2048;
    const int Mtot = Bt * S2;                  // 8192
    const long ts = (long)S2 * D;              // token-batch stride (elements)
    const long bs = (long)S2 * S2;             // scores batch stride
    const long wsz = (long)D * D;
    const float inv_std = 1.0f / sqrtf((float)D);

    dim3 blk(NT);
    dim3 gproj(D / BN, Mtot / BM, 1);          // (16, 64)
    dim3 gvt(Mtot / BN, D / BM, 1);            // (64, 16)
    dim3 gattn(S2 / BN, S2 / BM, Bt);          // (16, 16, 4)
    const unsigned gsx  = (unsigned)(ts * Bt / 4 / 256);
    const unsigned gsw  = (unsigned)(wsz / 4 / 256);

    // x split (used by q, k, vt)
    split_kernel<<<gsx, 256>>>(x, xh, xl, ts * Bt / 4);

    // q = x @ Wq^T + bq
    split_kernel<<<gsw, 256>>>(Wq, wh, wl, wsz / 4);
    mm<1, false, false, true><<<gproj, blk, SMEM_TOTAL>>>(
        xh, xl, wh, wl, bq, nullptr, qh, ql, D, D, D, D, 1.0f, 0, 0, 0);

    // k = x @ Wk^T + bk
    split_kernel<<<gsw, 256>>>(Wk, wh, wl, wsz / 4);
    mm<1, false, false, true><<<gproj, blk, SMEM_TOTAL>>>(
        xh, xl, wh, wl, bk, nullptr, kh, kl, D, D, D, D, 1.0f, 0, 0, 0);

    // vt[d,t] = sum_e Wv[d,e] x[t,e] + bv[d]  (V transposed, row bias)
    split_kernel<<<gsw, 256>>>(Wv, wh, wl, wsz / 4);
    mm<2, false, false, true><<<gvt, blk, SMEM_TOTAL>>>(
        wh, wl, xh, xl, bv, nullptr, vth, vtl, D, D, D, Mtot, 1.0f, 0, 0, 0);

    // scores = (q @ k^T) * inv_std, causal, fp32 out (into x's region; x dead)
    mm<0, true, false, false><<<gattn, blk, SMEM_TOTAL>>>(
        qh, ql, kh, kl, nullptr, s, nullptr, nullptr,
        D, D, D, S2, inv_std, ts, ts, bs);

    // softmax rows -> attn hi/lo (into q's region; q dead)
    softmax_split<<<Bt * S2, 256>>>(s, ah, al);

    // ctx[q,d] = sum_k attn[q,k] vt[d, z*S2+k]  (K-limited; into k's region)
    mm<0, false, true, true><<<gattn, blk, SMEM_TOTAL>>>(
        ah, al, vth, vtl, nullptr, nullptr, ch, cl,
        S2, S2, Mtot, D, 1.0f, bs, S2, ts);

    // out = ctx @ Wp^T + bp  (fp32 out)
    split_kernel<<<gsw, 256>>>(Wp, wh, wl, wsz / 4);
    mm<1, false, false, false><<<gproj, blk, SMEM_TOTAL>>>(
        ch, cl, wh, wl, bp, out, nullptr, nullptr, D, D, D, D, 1.0f, 0, 0, 0);
}